// round 10
// baseline (speedup 1.0000x reference)
#include <cuda_runtime.h>
#include <cuda_bf16.h>
#include <cstdint>

// Problem constants
#define BB 32
#define TT 512
#define DD 512
#define EE 8
#define HH 2048
#define FINAL_ELEMS (BB * TT * DD)

// ---------------- device scratch (no allocation allowed) --------------------
__device__ int g_expert[BB];
__device__ float g_pool_part[BB][16][DD];
__device__ __align__(16) __nv_bfloat16 g_x_hi[(size_t)BB * TT * DD];
__device__ __align__(16) __nv_bfloat16 g_x_lo[(size_t)BB * TT * DD];
__device__ __align__(16) __nv_bfloat16 g_w1_hi[(size_t)EE * HH * DD]; // [E][H][D] (K-major)
__device__ __align__(16) __nv_bfloat16 g_w1_lo[(size_t)EE * HH * DD];
__device__ __align__(16) __nv_bfloat16 g_w2_hi[(size_t)EE * DD * HH]; // [E][D][H] (K-major)
__device__ __align__(16) __nv_bfloat16 g_w2_lo[(size_t)EE * DD * HH];
__device__ __align__(16) __nv_bfloat16 g_h_hi[(size_t)BB * TT * HH];
__device__ __align__(16) __nv_bfloat16 g_h_lo[(size_t)BB * TT * HH];

// ---------------- PTX helpers (base-target only: cp.async/ldmatrix/mma) -----
__device__ __forceinline__ uint32_t smem_u32(const void* p) {
    uint32_t a;
    asm("{ .reg .u64 t; cvta.to.shared.u64 t, %1; cvt.u32.u64 %0, t; }" : "=r"(a) : "l"(p));
    return a;
}
#define CP_ASYNC16(s, g) \
    asm volatile("cp.async.cg.shared.global [%0], [%1], 16;" :: "r"(s), "l"(g))
#define CP_COMMIT() asm volatile("cp.async.commit_group;")
#define CP_WAIT(n)  asm volatile("cp.async.wait_group %0;" :: "n"(n))

__device__ __forceinline__ void ldsm4(uint32_t* r, uint32_t a) {
    asm volatile("ldmatrix.sync.aligned.m8n8.x4.shared.b16 {%0,%1,%2,%3}, [%4];"
                 : "=r"(r[0]), "=r"(r[1]), "=r"(r[2]), "=r"(r[3]) : "r"(a));
}
__device__ __forceinline__ void mma16816(float* c, const uint32_t* a, const uint32_t* b) {
    asm volatile("mma.sync.aligned.m16n8k16.row.col.f32.bf16.bf16.f32 "
                 "{%0,%1,%2,%3}, {%4,%5,%6,%7}, {%8,%9}, {%0,%1,%2,%3};"
                 : "+f"(c[0]), "+f"(c[1]), "+f"(c[2]), "+f"(c[3])
                 : "r"(a[0]), "r"(a[1]), "r"(a[2]), "r"(a[3]), "r"(b[0]), "r"(b[1]));
}

__device__ __forceinline__ void split2(float v, __nv_bfloat16& h, __nv_bfloat16& l) {
    h = __float2bfloat16(v);
    l = __float2bfloat16(v - __bfloat162float(h));
}

// ---------------- fused split(x) + partial mean pool ------------------------
// grid (BB, 16): block (b, ch) handles rows [ch*32, ch*32+32), all 512 cols.
__global__ void split_pool_x_kernel(const float* __restrict__ x) {
    const int b = blockIdx.x, ch = blockIdx.y;
    const size_t base = ((size_t)b * TT + ch * 32) * DD;
    const float* xb = x + base;
    const int c = threadIdx.x * 2;     // 0..510
    float s0 = 0.f, s1 = 0.f;
    #pragma unroll 4
    for (int t = 0; t < 32; t++) {
        const float2 v = *(const float2*)(xb + (size_t)t * DD + c);
        s0 += v.x; s1 += v.y;
        __nv_bfloat16 h0, l0, h1, l1;
        split2(v.x, h0, l0); split2(v.y, h1, l1);
        const size_t o = base + (size_t)t * DD + c;
        *(uint32_t*)(g_x_hi + o) =
            ((uint32_t)__bfloat16_as_ushort(h1) << 16) | __bfloat16_as_ushort(h0);
        *(uint32_t*)(g_x_lo + o) =
            ((uint32_t)__bfloat16_as_ushort(l1) << 16) | __bfloat16_as_ushort(l0);
    }
    g_pool_part[b][ch][c] = s0;
    g_pool_part[b][ch][c + 1] = s1;
}

// src [E][R][C] fp32 -> dst [E][C][R] split bf16 (which: 0=W1, 1=W2)
__global__ void transpose_split_kernel(const float* __restrict__ src, int R, int C, int which) {
    __shared__ float tile[32][33];
    const int e = blockIdx.z;
    const int c0 = blockIdx.x * 32, r0 = blockIdx.y * 32;
    const int tx = threadIdx.x, ty = threadIdx.y;
    const float* s = src + (size_t)e * R * C;
    #pragma unroll
    for (int i = 0; i < 32; i += 8)
        tile[ty + i][tx] = s[(size_t)(r0 + ty + i) * C + c0 + tx];
    __syncthreads();
    __nv_bfloat16* dh = (which ? g_w2_hi : g_w1_hi) + (size_t)e * R * C;
    __nv_bfloat16* dl = (which ? g_w2_lo : g_w1_lo) + (size_t)e * R * C;
    #pragma unroll
    for (int i = 0; i < 32; i += 8) {
        float v = tile[tx][ty + i];
        __nv_bfloat16 h, l;
        split2(v, h, l);
        dh[(size_t)(c0 + ty + i) * R + r0 + tx] = h;
        dl[(size_t)(c0 + ty + i) * R + r0 + tx] = l;
    }
}

// ---------------- router ----------------------------------------------------
__global__ void router_kernel(const float* __restrict__ Wp, const float* __restrict__ bp,
                              float* __restrict__ out, int write_aux) {
    __shared__ float pooled[DD];
    __shared__ float logits[EE];
    const int b = blockIdx.x;
    for (int d = threadIdx.x; d < DD; d += 256) {
        float s = 0.f;
        #pragma unroll
        for (int ch = 0; ch < 16; ch++) s += g_pool_part[b][ch][d];
        pooled[d] = s * (1.0f / TT);
    }
    __syncthreads();
    const int warp = threadIdx.x >> 5, lane = threadIdx.x & 31;
    if (warp < EE) {
        float s = 0.f;
        for (int d = lane; d < DD; d += 32) s += pooled[d] * Wp[d * EE + warp];
        #pragma unroll
        for (int o = 16; o > 0; o >>= 1) s += __shfl_xor_sync(0xFFFFFFFFu, s, o);
        if (lane == 0) logits[warp] = s + bp[warp];
    }
    __syncthreads();
    if (threadIdx.x == 0) {
        float mx = logits[0]; int arg = 0;
        #pragma unroll
        for (int e = 1; e < EE; e++) if (logits[e] > mx) { mx = logits[e]; arg = e; }
        float ex[EE], den = 0.f;
        #pragma unroll
        for (int e = 0; e < EE; e++) { ex[e] = expf(logits[e] - mx); den += ex[e]; }
        if (write_aux) {
            const float inv = 1.0f / den;
            #pragma unroll
            for (int e = 0; e < EE; e++) out[FINAL_ELEMS + b * EE + e] = ex[e] * inv;
            out[FINAL_ELEMS + BB * EE + b] = (float)arg;
        }
        g_expert[b] = arg;
    }
}

// ---------------- HMMA GEMM (mma.sync, split-bf16 3-term) -------------------
// Block 128x128, KC=32, THREE-stage cp.async ring, ONE __syncthreads per iter.
// 8 warps (4Mx2N), warp tile 32x64, XOR-swizzled smem for conflict-free ldmatrix.
#define KC 32
#define AHI_OFF 0
#define ALO_OFF 8192
#define BHI_OFF 16384
#define BLO_OFF 24576
#define STAGE_B 32768
#define NSTAGE 3
#define SMEM_TOTAL (NSTAGE * STAGE_B)

// smem byte offset for (row r, 16B-chunk c) with swizzle
__device__ __forceinline__ uint32_t swoff(int r, int c) {
    return (uint32_t)(r * 64 + ((c ^ ((r >> 1) & 3)) << 4));
}

template<bool RELU, bool SPLIT_OUT>
__device__ __forceinline__ void gemm_hmma(
    const __nv_bfloat16* __restrict__ Ahi, const __nv_bfloat16* __restrict__ Alo,
    const __nv_bfloat16* __restrict__ Bhi, const __nv_bfloat16* __restrict__ Blo,
    const float* __restrict__ bias, int K,
    float* __restrict__ outF, __nv_bfloat16* __restrict__ outHi,
    __nv_bfloat16* __restrict__ outLo, int Nld) {

    extern __shared__ char smem[];
    const uint32_t sb = smem_u32(smem);
    const int tid = threadIdx.x;
    const int wid = tid >> 5, lane = tid & 31;
    const int wm = wid & 3, wn = wid >> 2;          // 4 x 2 warp grid
    const int row0 = blockIdx.y * 128;
    const int col0 = blockIdx.x * 128;

    float acc[2][8][4];
    #pragma unroll
    for (int i = 0; i < 2; i++)
        #pragma unroll
        for (int j = 0; j < 8; j++)
            #pragma unroll
            for (int k = 0; k < 4; k++) acc[i][j][k] = 0.f;

    const int nk = K / KC;
    const int sr = tid >> 2, sc = tid & 3;          // staging: 2 chunks per array

    // stage loads for chunk IDX into ring buffer IDX%3 (no commit inside)
    #define STAGE_LOADS(IDX)                                                    \
    do {                                                                        \
        const int _i = (IDX);                                                   \
        const uint32_t _d = sb + (uint32_t)(_i % NSTAGE) * STAGE_B;             \
        const int _kb = _i * KC;                                                \
        _Pragma("unroll")                                                       \
        for (int it = 0; it < 2; it++) {                                        \
            const int r = sr + it * 64;                                         \
            const uint32_t so = swoff(r, sc);                                   \
            const size_t ga = (size_t)(row0 + r) * K + _kb + sc * 8;            \
            const size_t gb = (size_t)(col0 + r) * K + _kb + sc * 8;            \
            CP_ASYNC16(_d + AHI_OFF + so, Ahi + ga);                            \
            CP_ASYNC16(_d + ALO_OFF + so, Alo + ga);                            \
            CP_ASYNC16(_d + BHI_OFF + so, Bhi + gb);                            \
            CP_ASYNC16(_d + BLO_OFF + so, Blo + gb);                            \
        }                                                                       \
    } while (0)

    // prologue: fill 2 stages (nk >= 2 always here)
    STAGE_LOADS(0); CP_COMMIT();
    STAGE_LOADS(1); CP_COMMIT();

    // fragment address parameters (constant across loop)
    const int a_mrow = lane & 15, a_kh = lane >> 4;
    const int b_nr = lane & 7, b_kh = (lane >> 3) & 1, b_nt = lane >> 4;

    for (int i = 0; i < nk; i++) {
        CP_WAIT(1);              // this thread's stage-i group complete
        __syncthreads();         // all threads' stage-i data visible; iter i-1 reads done

        // refill: write buffer (i+2)%3, last read at iter i-1 (already drained)
        if (i + 2 < nk) STAGE_LOADS(i + 2);
        CP_COMMIT();             // always commit to keep CP_WAIT(1) accounting valid

        const uint32_t st = sb + (uint32_t)(i % NSTAGE) * STAGE_B;
        #pragma unroll
        for (int ks = 0; ks < 2; ks++) {
            uint32_t ah[2][4], al[2][4];
            #pragma unroll
            for (int mt = 0; mt < 2; mt++) {
                const int r = wm * 32 + mt * 16 + a_mrow;
                const uint32_t ad = st + swoff(r, ks * 2 + a_kh);
                ldsm4(ah[mt], ad + AHI_OFF);
                ldsm4(al[mt], ad + ALO_OFF);
            }
            uint32_t bh[8][2], bl[8][2];
            #pragma unroll
            for (int ng = 0; ng < 4; ng++) {
                const int r = wn * 64 + ng * 16 + b_nt * 8 + b_nr;
                const uint32_t bd = st + swoff(r, ks * 2 + b_kh);
                uint32_t t4[4];
                ldsm4(t4, bd + BHI_OFF);
                bh[ng * 2][0] = t4[0]; bh[ng * 2][1] = t4[1];
                bh[ng * 2 + 1][0] = t4[2]; bh[ng * 2 + 1][1] = t4[3];
                ldsm4(t4, bd + BLO_OFF);
                bl[ng * 2][0] = t4[0]; bl[ng * 2][1] = t4[1];
                bl[ng * 2 + 1][0] = t4[2]; bl[ng * 2 + 1][1] = t4[3];
            }
            #pragma unroll
            for (int mt = 0; mt < 2; mt++)
                #pragma unroll
                for (int nt = 0; nt < 8; nt++) {
                    mma16816(acc[mt][nt], ah[mt], bh[nt]);   // hi*hi
                    mma16816(acc[mt][nt], ah[mt], bl[nt]);   // hi*lo
                    mma16816(acc[mt][nt], al[mt], bh[nt]);   // lo*hi
                }
        }
        // NO trailing sync: next iter's top sync orders buffer reuse
    }
    #undef STAGE_LOADS

    // ---- epilogue: bias (+relu), direct stores ----
    const int erow = lane >> 2, ecol = (lane & 3) * 2;
    #pragma unroll
    for (int mt = 0; mt < 2; mt++) {
        #pragma unroll
        for (int nt = 0; nt < 8; nt++) {
            const int col = col0 + wn * 64 + nt * 8 + ecol;
            const float bx = __ldg(bias + col), by = __ldg(bias + col + 1);
            float v[4];
            v[0] = acc[mt][nt][0] + bx; v[1] = acc[mt][nt][1] + by;
            v[2] = acc[mt][nt][2] + bx; v[3] = acc[mt][nt][3] + by;
            if (RELU) {
                #pragma unroll
                for (int q = 0; q < 4; q++) v[q] = fmaxf(v[q], 0.f);
            }
            const size_t r0g = (size_t)(row0 + wm * 32 + mt * 16 + erow);
            #pragma unroll
            for (int half = 0; half < 2; half++) {
                const size_t row = r0g + half * 8;
                const float v0 = v[half * 2], v1 = v[half * 2 + 1];
                if (SPLIT_OUT) {
                    __nv_bfloat16 h0, l0, h1, l1;
                    split2(v0, h0, l0); split2(v1, h1, l1);
                    *(uint32_t*)(outHi + row * Nld + col) =
                        ((uint32_t)__bfloat16_as_ushort(h1) << 16) | __bfloat16_as_ushort(h0);
                    *(uint32_t*)(outLo + row * Nld + col) =
                        ((uint32_t)__bfloat16_as_ushort(l1) << 16) | __bfloat16_as_ushort(l0);
                } else {
                    float2 f2; f2.x = v0; f2.y = v1;
                    *(float2*)(outF + row * Nld + col) = f2;
                }
            }
        }
    }
}

// GEMM1: h = relu(x @ W1[e] + b1[e])   M=512, N=2048, K=512
__global__ void __launch_bounds__(256, 1)
gemm1_mm(const float* __restrict__ b1) {
    const int b = blockIdx.z;
    const int e = g_expert[b];
    gemm_hmma<true, true>(g_x_hi + (size_t)b * TT * DD, g_x_lo + (size_t)b * TT * DD,
                          g_w1_hi + (size_t)e * HH * DD, g_w1_lo + (size_t)e * HH * DD,
                          b1 + e * HH, DD,
                          nullptr, g_h_hi + (size_t)b * TT * HH, g_h_lo + (size_t)b * TT * HH, HH);
}

// GEMM2: out = h @ W2[e] + b2[e]       M=512, N=512, K=2048
__global__ void __launch_bounds__(256, 1)
gemm2_mm(const float* __restrict__ b2, float* __restrict__ out) {
    const int b = blockIdx.z;
    const int e = g_expert[b];
    gemm_hmma<false, false>(g_h_hi + (size_t)b * TT * HH, g_h_lo + (size_t)b * TT * HH,
                            g_w2_hi + (size_t)e * DD * HH, g_w2_lo + (size_t)e * DD * HH,
                            b2 + e * DD, HH,
                            out + (size_t)b * TT * DD, nullptr, nullptr, DD);
}

// ---------------- launch ----------------------------------------------------
extern "C" void kernel_launch(void* const* d_in, const int* in_sizes, int n_in,
                              void* d_out, int out_size) {
    const float* x  = (const float*)d_in[0];
    const float* Wp = (const float*)d_in[1];
    const float* bp = (const float*)d_in[2];
    const float* W1 = (const float*)d_in[3];
    const float* b1 = (const float*)d_in[4];
    const float* W2 = (const float*)d_in[5];
    const float* b2 = (const float*)d_in[6];
    float* out = (float*)d_out;

    const int write_aux = (out_size >= FINAL_ELEMS + BB * EE + BB) ? 1 : 0;

    cudaFuncSetAttribute(gemm1_mm, cudaFuncAttributeMaxDynamicSharedMemorySize, SMEM_TOTAL);
    cudaFuncSetAttribute(gemm2_mm, cudaFuncAttributeMaxDynamicSharedMemorySize, SMEM_TOTAL);

    split_pool_x_kernel<<<dim3(BB, 16), 256>>>(x);
    transpose_split_kernel<<<dim3(HH / 32, DD / 32, EE), dim3(32, 8)>>>(W1, DD, HH, 0);
    transpose_split_kernel<<<dim3(DD / 32, HH / 32, EE), dim3(32, 8)>>>(W2, HH, DD, 1);
    router_kernel<<<BB, 256>>>(Wp, bp, out, write_aux);
    gemm1_mm<<<dim3(HH / 128, TT / 128, BB), 256, SMEM_TOTAL>>>(b1);
    gemm2_mm<<<dim3(DD / 128, TT / 128, BB), 256, SMEM_TOTAL>>>(b2, out);
}

// round 12
// speedup vs baseline: 1.1275x; 1.1275x over previous
#include <cuda_runtime.h>
#include <cuda_bf16.h>
#include <cstdint>

// Problem constants
#define BB 32
#define TT 512
#define DD 512
#define EE 8
#define HH 2048
#define FINAL_ELEMS (BB * TT * DD)

// ---------------- device scratch (no allocation allowed) --------------------
__device__ int g_expert[BB];
__device__ float g_pool_part[BB][16][DD];
__device__ __align__(16) __nv_bfloat16 g_x_hi[(size_t)BB * TT * DD];
__device__ __align__(16) __nv_bfloat16 g_x_lo[(size_t)BB * TT * DD];
__device__ __align__(16) __nv_bfloat16 g_w1_hi[(size_t)EE * HH * DD]; // [E][H][D] (K-major)
__device__ __align__(16) __nv_bfloat16 g_w1_lo[(size_t)EE * HH * DD];
__device__ __align__(16) __nv_bfloat16 g_w2_hi[(size_t)EE * DD * HH]; // [E][D][H] (K-major)
__device__ __align__(16) __nv_bfloat16 g_w2_lo[(size_t)EE * DD * HH];
__device__ __align__(16) __nv_bfloat16 g_h_hi[(size_t)BB * TT * HH];
__device__ __align__(16) __nv_bfloat16 g_h_lo[(size_t)BB * TT * HH];

// ---------------- PTX helpers (base-target only: cp.async/ldmatrix/mma) -----
__device__ __forceinline__ uint32_t smem_u32(const void* p) {
    uint32_t a;
    asm("{ .reg .u64 t; cvta.to.shared.u64 t, %1; cvt.u32.u64 %0, t; }" : "=r"(a) : "l"(p));
    return a;
}
#define CP_ASYNC16(s, g) \
    asm volatile("cp.async.cg.shared.global [%0], [%1], 16;" :: "r"(s), "l"(g))
#define CP_COMMIT() asm volatile("cp.async.commit_group;")
#define CP_WAIT(n)  asm volatile("cp.async.wait_group %0;" :: "n"(n))

__device__ __forceinline__ void ldsm4(uint32_t* r, uint32_t a) {
    asm volatile("ldmatrix.sync.aligned.m8n8.x4.shared.b16 {%0,%1,%2,%3}, [%4];"
                 : "=r"(r[0]), "=r"(r[1]), "=r"(r[2]), "=r"(r[3]) : "r"(a));
}
__device__ __forceinline__ void mma16816(float* c, const uint32_t* a, const uint32_t* b) {
    asm volatile("mma.sync.aligned.m16n8k16.row.col.f32.bf16.bf16.f32 "
                 "{%0,%1,%2,%3}, {%4,%5,%6,%7}, {%8,%9}, {%0,%1,%2,%3};"
                 : "+f"(c[0]), "+f"(c[1]), "+f"(c[2]), "+f"(c[3])
                 : "r"(a[0]), "r"(a[1]), "r"(a[2]), "r"(a[3]), "r"(b[0]), "r"(b[1]));
}

__device__ __forceinline__ void split2(float v, __nv_bfloat16& h, __nv_bfloat16& l) {
    h = __float2bfloat16(v);
    l = __float2bfloat16(v - __bfloat162float(h));
}

// ---------------- fused split(x) + partial mean pool ------------------------
// grid (BB, 16): block (b, ch) handles rows [ch*32, ch*32+32), all 512 cols.
__global__ void split_pool_x_kernel(const float* __restrict__ x) {
    const int b = blockIdx.x, ch = blockIdx.y;
    const size_t base = ((size_t)b * TT + ch * 32) * DD;
    const float* xb = x + base;
    const int c = threadIdx.x * 2;     // 0..510
    float s0 = 0.f, s1 = 0.f;
    #pragma unroll 4
    for (int t = 0; t < 32; t++) {
        const float2 v = *(const float2*)(xb + (size_t)t * DD + c);
        s0 += v.x; s1 += v.y;
        __nv_bfloat16 h0, l0, h1, l1;
        split2(v.x, h0, l0); split2(v.y, h1, l1);
        const size_t o = base + (size_t)t * DD + c;
        *(uint32_t*)(g_x_hi + o) =
            ((uint32_t)__bfloat16_as_ushort(h1) << 16) | __bfloat16_as_ushort(h0);
        *(uint32_t*)(g_x_lo + o) =
            ((uint32_t)__bfloat16_as_ushort(l1) << 16) | __bfloat16_as_ushort(l0);
    }
    g_pool_part[b][ch][c] = s0;
    g_pool_part[b][ch][c + 1] = s1;
}

// src [E][R][C] fp32 -> dst [E][C][R] split bf16 (which: 0=W1, 1=W2)
__global__ void transpose_split_kernel(const float* __restrict__ src, int R, int C, int which) {
    __shared__ float tile[32][33];
    const int e = blockIdx.z;
    const int c0 = blockIdx.x * 32, r0 = blockIdx.y * 32;
    const int tx = threadIdx.x, ty = threadIdx.y;
    const float* s = src + (size_t)e * R * C;
    #pragma unroll
    for (int i = 0; i < 32; i += 8)
        tile[ty + i][tx] = s[(size_t)(r0 + ty + i) * C + c0 + tx];
    __syncthreads();
    __nv_bfloat16* dh = (which ? g_w2_hi : g_w1_hi) + (size_t)e * R * C;
    __nv_bfloat16* dl = (which ? g_w2_lo : g_w1_lo) + (size_t)e * R * C;
    #pragma unroll
    for (int i = 0; i < 32; i += 8) {
        float v = tile[tx][ty + i];
        __nv_bfloat16 h, l;
        split2(v, h, l);
        dh[(size_t)(c0 + ty + i) * R + r0 + tx] = h;
        dl[(size_t)(c0 + ty + i) * R + r0 + tx] = l;
    }
}

// ---------------- router ----------------------------------------------------
__global__ void router_kernel(const float* __restrict__ Wp, const float* __restrict__ bp,
                              float* __restrict__ out, int write_aux) {
    __shared__ float pooled[DD];
    __shared__ float logits[EE];
    const int b = blockIdx.x;
    for (int d = threadIdx.x; d < DD; d += 256) {
        float s = 0.f;
        #pragma unroll
        for (int ch = 0; ch < 16; ch++) s += g_pool_part[b][ch][d];
        pooled[d] = s * (1.0f / TT);
    }
    __syncthreads();
    const int warp = threadIdx.x >> 5, lane = threadIdx.x & 31;
    if (warp < EE) {
        float s = 0.f;
        for (int d = lane; d < DD; d += 32) s += pooled[d] * Wp[d * EE + warp];
        #pragma unroll
        for (int o = 16; o > 0; o >>= 1) s += __shfl_xor_sync(0xFFFFFFFFu, s, o);
        if (lane == 0) logits[warp] = s + bp[warp];
    }
    __syncthreads();
    if (threadIdx.x == 0) {
        float mx = logits[0]; int arg = 0;
        #pragma unroll
        for (int e = 1; e < EE; e++) if (logits[e] > mx) { mx = logits[e]; arg = e; }
        float ex[EE], den = 0.f;
        #pragma unroll
        for (int e = 0; e < EE; e++) { ex[e] = expf(logits[e] - mx); den += ex[e]; }
        if (write_aux) {
            const float inv = 1.0f / den;
            #pragma unroll
            for (int e = 0; e < EE; e++) out[FINAL_ELEMS + b * EE + e] = ex[e] * inv;
            out[FINAL_ELEMS + BB * EE + b] = (float)arg;
        }
        g_expert[b] = arg;
    }
}

// ---------------- HMMA GEMM (mma.sync, split-bf16 3-term) -------------------
// Block 128x128, KC=64, double-buffered cp.async stages (R8-proven ordering),
// 8 warps (4Mx2N), warp tile 32x64, XOR-swizzled 128B rows (c ^= r&7).
#define KC 64
#define AHI_OFF 0
#define ALO_OFF 16384
#define BHI_OFF 32768
#define BLO_OFF 49152
#define STAGE_B 65536
#define SMEM_TOTAL (2 * STAGE_B)

// smem byte offset for (row r, 16B-chunk c in 0..7) with swizzle
__device__ __forceinline__ uint32_t swoff(int r, int c) {
    return (uint32_t)(r * 128 + ((c ^ (r & 7)) << 4));
}

template<bool RELU, bool SPLIT_OUT>
__device__ __forceinline__ void gemm_hmma(
    const __nv_bfloat16* __restrict__ Ahi, const __nv_bfloat16* __restrict__ Alo,
    const __nv_bfloat16* __restrict__ Bhi, const __nv_bfloat16* __restrict__ Blo,
    const float* __restrict__ bias, int K,
    float* __restrict__ outF, __nv_bfloat16* __restrict__ outHi,
    __nv_bfloat16* __restrict__ outLo, int Nld) {

    extern __shared__ char smem[];
    const uint32_t sb = smem_u32(smem);
    const int tid = threadIdx.x;
    const int wid = tid >> 5, lane = tid & 31;
    const int wm = wid & 3, wn = wid >> 2;          // 4 x 2 warp grid
    const int row0 = blockIdx.y * 128;
    const int col0 = blockIdx.x * 128;

    float acc[2][8][4];
    #pragma unroll
    for (int i = 0; i < 2; i++)
        #pragma unroll
        for (int j = 0; j < 8; j++)
            #pragma unroll
            for (int k = 0; k < 4; k++) acc[i][j][k] = 0.f;

    const int nk = K / KC;                          // 8 or 32
    const int sr = tid >> 3, sc = tid & 7;          // staging: 32 rows/pass, 8 chunks/row

    // ---- stage helper: 4 passes x 4 arrays = 16 cp.async per thread ----
    #define STAGE(IDX)                                                          \
    do {                                                                        \
        const int _i = (IDX);                                                   \
        const uint32_t _d = sb + (uint32_t)(_i & 1) * STAGE_B;                  \
        const int _kb = _i * KC;                                                \
        _Pragma("unroll")                                                       \
        for (int p = 0; p < 4; p++) {                                           \
            const int r = sr + p * 32;                                          \
            const uint32_t so = swoff(r, sc);                                   \
            const size_t ga = (size_t)(row0 + r) * K + _kb + sc * 8;            \
            const size_t gb = (size_t)(col0 + r) * K + _kb + sc * 8;            \
            CP_ASYNC16(_d + AHI_OFF + so, Ahi + ga);                            \
            CP_ASYNC16(_d + ALO_OFF + so, Alo + ga);                            \
            CP_ASYNC16(_d + BHI_OFF + so, Bhi + gb);                            \
            CP_ASYNC16(_d + BLO_OFF + so, Blo + gb);                            \
        }                                                                       \
        CP_COMMIT();                                                            \
    } while (0)

    STAGE(0);

    // fragment address parameters (constant across loop)
    const int a_mrow = lane & 15, a_kh = lane >> 4;
    const int b_nr = lane & 7, b_kh = (lane >> 3) & 1, b_nt = lane >> 4;

    for (int i = 0; i < nk; i++) {
        if (i + 1 < nk) { STAGE(i + 1); CP_WAIT(1); }
        else            { CP_WAIT(0); }
        __syncthreads();

        const uint32_t st = sb + (uint32_t)(i & 1) * STAGE_B;
        #pragma unroll
        for (int ks = 0; ks < 4; ks++) {            // 4 x k16 sub-chunks
            uint32_t ah[2][4], al[2][4];
            #pragma unroll
            for (int mt = 0; mt < 2; mt++) {
                const int r = wm * 32 + mt * 16 + a_mrow;
                const uint32_t ad = st + swoff(r, ks * 2 + a_kh);
                ldsm4(ah[mt], ad + AHI_OFF);
                ldsm4(al[mt], ad + ALO_OFF);
            }
            uint32_t bh[8][2], bl[8][2];
            #pragma unroll
            for (int ng = 0; ng < 4; ng++) {
                const int r = wn * 64 + ng * 16 + b_nt * 8 + b_nr;
                const uint32_t bd = st + swoff(r, ks * 2 + b_kh);
                uint32_t t4[4];
                ldsm4(t4, bd + BHI_OFF);
                bh[ng * 2][0] = t4[0]; bh[ng * 2][1] = t4[1];
                bh[ng * 2 + 1][0] = t4[2]; bh[ng * 2 + 1][1] = t4[3];
                ldsm4(t4, bd + BLO_OFF);
                bl[ng * 2][0] = t4[0]; bl[ng * 2][1] = t4[1];
                bl[ng * 2 + 1][0] = t4[2]; bl[ng * 2 + 1][1] = t4[3];
            }
            #pragma unroll
            for (int mt = 0; mt < 2; mt++)
                #pragma unroll
                for (int nt = 0; nt < 8; nt++) {
                    mma16816(acc[mt][nt], ah[mt], bh[nt]);   // hi*hi
                    mma16816(acc[mt][nt], ah[mt], bl[nt]);   // hi*lo
                    mma16816(acc[mt][nt], al[mt], bh[nt]);   // lo*hi
                }
        }
        __syncthreads();
    }
    #undef STAGE

    // ---- epilogue: bias (+relu), direct stores ----
    const int erow = lane >> 2, ecol = (lane & 3) * 2;
    #pragma unroll
    for (int mt = 0; mt < 2; mt++) {
        #pragma unroll
        for (int nt = 0; nt < 8; nt++) {
            const int col = col0 + wn * 64 + nt * 8 + ecol;
            const float bx = __ldg(bias + col), by = __ldg(bias + col + 1);
            float v[4];
            v[0] = acc[mt][nt][0] + bx; v[1] = acc[mt][nt][1] + by;
            v[2] = acc[mt][nt][2] + bx; v[3] = acc[mt][nt][3] + by;
            if (RELU) {
                #pragma unroll
                for (int q = 0; q < 4; q++) v[q] = fmaxf(v[q], 0.f);
            }
            const size_t r0g = (size_t)(row0 + wm * 32 + mt * 16 + erow);
            #pragma unroll
            for (int half = 0; half < 2; half++) {
                const size_t row = r0g + half * 8;
                const float v0 = v[half * 2], v1 = v[half * 2 + 1];
                if (SPLIT_OUT) {
                    __nv_bfloat16 h0, l0, h1, l1;
                    split2(v0, h0, l0); split2(v1, h1, l1);
                    *(uint32_t*)(outHi + row * Nld + col) =
                        ((uint32_t)__bfloat16_as_ushort(h1) << 16) | __bfloat16_as_ushort(h0);
                    *(uint32_t*)(outLo + row * Nld + col) =
                        ((uint32_t)__bfloat16_as_ushort(l1) << 16) | __bfloat16_as_ushort(l0);
                } else {
                    float2 f2; f2.x = v0; f2.y = v1;
                    *(float2*)(outF + row * Nld + col) = f2;
                }
            }
        }
    }
}

// GEMM1: h = relu(x @ W1[e] + b1[e])   M=512, N=2048, K=512
__global__ void __launch_bounds__(256, 1)
gemm1_mm(const float* __restrict__ b1) {
    const int b = blockIdx.z;
    const int e = g_expert[b];
    gemm_hmma<true, true>(g_x_hi + (size_t)b * TT * DD, g_x_lo + (size_t)b * TT * DD,
                          g_w1_hi + (size_t)e * HH * DD, g_w1_lo + (size_t)e * HH * DD,
                          b1 + e * HH, DD,
                          nullptr, g_h_hi + (size_t)b * TT * HH, g_h_lo + (size_t)b * TT * HH, HH);
}

// GEMM2: out = h @ W2[e] + b2[e]       M=512, N=512, K=2048
__global__ void __launch_bounds__(256, 1)
gemm2_mm(const float* __restrict__ b2, float* __restrict__ out) {
    const int b = blockIdx.z;
    const int e = g_expert[b];
    gemm_hmma<false, false>(g_h_hi + (size_t)b * TT * HH, g_h_lo + (size_t)b * TT * HH,
                            g_w2_hi + (size_t)e * DD * HH, g_w2_lo + (size_t)e * DD * HH,
                            b2 + e * DD, HH,
                            out + (size_t)b * TT * DD, nullptr, nullptr, DD);
}

// ---------------- launch ----------------------------------------------------
extern "C" void kernel_launch(void* const* d_in, const int* in_sizes, int n_in,
                              void* d_out, int out_size) {
    const float* x  = (const float*)d_in[0];
    const float* Wp = (const float*)d_in[1];
    const float* bp = (const float*)d_in[2];
    const float* W1 = (const float*)d_in[3];
    const float* b1 = (const float*)d_in[4];
    const float* W2 = (const float*)d_in[5];
    const float* b2 = (const float*)d_in[6];
    float* out = (float*)d_out;

    const int write_aux = (out_size >= FINAL_ELEMS + BB * EE + BB) ? 1 : 0;

    cudaFuncSetAttribute(gemm1_mm, cudaFuncAttributeMaxDynamicSharedMemorySize, SMEM_TOTAL);
    cudaFuncSetAttribute(gemm2_mm, cudaFuncAttributeMaxDynamicSharedMemorySize, SMEM_TOTAL);

    split_pool_x_kernel<<<dim3(BB, 16), 256>>>(x);
    transpose_split_kernel<<<dim3(HH / 32, DD / 32, EE), dim3(32, 8)>>>(W1, DD, HH, 0);
    transpose_split_kernel<<<dim3(DD / 32, HH / 32, EE), dim3(32, 8)>>>(W2, HH, DD, 1);
    router_kernel<<<BB, 256>>>(Wp, bp, out, write_aux);
    gemm1_mm<<<dim3(HH / 128, TT / 128, BB), 256, SMEM_TOTAL>>>(b1);
    gemm2_mm<<<dim3(DD / 128, TT / 128, BB), 256, SMEM_TOTAL>>>(b2, out);
}

// round 15
// speedup vs baseline: 1.7583x; 1.5595x over previous
#include <cuda_runtime.h>
#include <cuda_bf16.h>
#include <cstdint>

// Problem constants
#define BB 32
#define TT 512
#define DD 512
#define EE 8
#define HH 2048
#define FINAL_ELEMS (BB * TT * DD)

// ---------------- device scratch (no allocation allowed) --------------------
__device__ int g_expert[BB];
__device__ float g_pool_part[BB][16][DD];
__device__ __align__(16) __nv_bfloat16 g_x_hi[(size_t)BB * TT * DD];
__device__ __align__(16) __nv_bfloat16 g_x_lo[(size_t)BB * TT * DD];
__device__ __align__(16) __nv_bfloat16 g_w1_hi[(size_t)EE * HH * DD]; // [E][H][D] (K-major)
__device__ __align__(16) __nv_bfloat16 g_w1_lo[(size_t)EE * HH * DD];
__device__ __align__(16) __nv_bfloat16 g_w2_hi[(size_t)EE * DD * HH]; // [E][D][H] (K-major)
__device__ __align__(16) __nv_bfloat16 g_w2_lo[(size_t)EE * DD * HH];
__device__ __align__(16) __nv_bfloat16 g_h_hi[(size_t)BB * TT * HH];
__device__ __align__(16) __nv_bfloat16 g_h_lo[(size_t)BB * TT * HH];

// ---------------- PTX helpers (base-target only: cp.async/ldmatrix/mma) -----
__device__ __forceinline__ uint32_t smem_u32(const void* p) {
    uint32_t a;
    asm("{ .reg .u64 t; cvta.to.shared.u64 t, %1; cvt.u32.u64 %0, t; }" : "=r"(a) : "l"(p));
    return a;
}
#define CP_ASYNC16(s, g) \
    asm volatile("cp.async.cg.shared.global [%0], [%1], 16;" :: "r"(s), "l"(g))
#define CP_COMMIT() asm volatile("cp.async.commit_group;")
#define CP_WAIT(n)  asm volatile("cp.async.wait_group %0;" :: "n"(n))

__device__ __forceinline__ void ldsm4(uint32_t* r, uint32_t a) {
    asm volatile("ldmatrix.sync.aligned.m8n8.x4.shared.b16 {%0,%1,%2,%3}, [%4];"
                 : "=r"(r[0]), "=r"(r[1]), "=r"(r[2]), "=r"(r[3]) : "r"(a));
}
__device__ __forceinline__ void mma16816(float* c, const uint32_t* a, const uint32_t* b) {
    asm volatile("mma.sync.aligned.m16n8k16.row.col.f32.bf16.bf16.f32 "
                 "{%0,%1,%2,%3}, {%4,%5,%6,%7}, {%8,%9}, {%0,%1,%2,%3};"
                 : "+f"(c[0]), "+f"(c[1]), "+f"(c[2]), "+f"(c[3])
                 : "r"(a[0]), "r"(a[1]), "r"(a[2]), "r"(a[3]), "r"(b[0]), "r"(b[1]));
}

__device__ __forceinline__ void split2(float v, __nv_bfloat16& h, __nv_bfloat16& l) {
    h = __float2bfloat16(v);
    l = __float2bfloat16(v - __bfloat162float(h));
}

// ---------------- fused split(x) + partial mean pool ------------------------
__global__ void split_pool_x_kernel(const float* __restrict__ x) {
    const int b = blockIdx.x, ch = blockIdx.y;
    const size_t base = ((size_t)b * TT + ch * 32) * DD;
    const float* xb = x + base;
    const int c = threadIdx.x * 2;     // 0..510
    float s0 = 0.f, s1 = 0.f;
    #pragma unroll 4
    for (int t = 0; t < 32; t++) {
        const float2 v = *(const float2*)(xb + (size_t)t * DD + c);
        s0 += v.x; s1 += v.y;
        __nv_bfloat16 h0, l0, h1, l1;
        split2(v.x, h0, l0); split2(v.y, h1, l1);
        const size_t o = base + (size_t)t * DD + c;
        *(uint32_t*)(g_x_hi + o) =
            ((uint32_t)__bfloat16_as_ushort(h1) << 16) | __bfloat16_as_ushort(h0);
        *(uint32_t*)(g_x_lo + o) =
            ((uint32_t)__bfloat16_as_ushort(l1) << 16) | __bfloat16_as_ushort(l0);
    }
    g_pool_part[b][ch][c] = s0;
    g_pool_part[b][ch][c + 1] = s1;
}

// src [E][R][C] fp32 -> dst [E][C][R] split bf16 (which: 0=W1, 1=W2)
__global__ void transpose_split_kernel(const float* __restrict__ src, int R, int C, int which) {
    __shared__ float tile[32][33];
    const int e = blockIdx.z;
    const int c0 = blockIdx.x * 32, r0 = blockIdx.y * 32;
    const int tx = threadIdx.x, ty = threadIdx.y;
    const float* s = src + (size_t)e * R * C;
    #pragma unroll
    for (int i = 0; i < 32; i += 8)
        tile[ty + i][tx] = s[(size_t)(r0 + ty + i) * C + c0 + tx];
    __syncthreads();
    __nv_bfloat16* dh = (which ? g_w2_hi : g_w1_hi) + (size_t)e * R * C;
    __nv_bfloat16* dl = (which ? g_w2_lo : g_w1_lo) + (size_t)e * R * C;
    #pragma unroll
    for (int i = 0; i < 32; i += 8) {
        float v = tile[tx][ty + i];
        __nv_bfloat16 h, l;
        split2(v, h, l);
        dh[(size_t)(c0 + ty + i) * R + r0 + tx] = h;
        dl[(size_t)(c0 + ty + i) * R + r0 + tx] = l;
    }
}

// ---------------- router ----------------------------------------------------
__global__ void router_kernel(const float* __restrict__ Wp, const float* __restrict__ bp,
                              float* __restrict__ out, int write_aux) {
    __shared__ float pooled[DD];
    __shared__ float logits[EE];
    const int b = blockIdx.x;
    for (int d = threadIdx.x; d < DD; d += 256) {
        float s = 0.f;
        #pragma unroll
        for (int ch = 0; ch < 16; ch++) s += g_pool_part[b][ch][d];
        pooled[d] = s * (1.0f / TT);
    }
    __syncthreads();
    const int warp = threadIdx.x >> 5, lane = threadIdx.x & 31;
    if (warp < EE) {
        float s = 0.f;
        for (int d = lane; d < DD; d += 32) s += pooled[d] * Wp[d * EE + warp];
        #pragma unroll
        for (int o = 16; o > 0; o >>= 1) s += __shfl_xor_sync(0xFFFFFFFFu, s, o);
        if (lane == 0) logits[warp] = s + bp[warp];
    }
    __syncthreads();
    if (threadIdx.x == 0) {
        float mx = logits[0]; int arg = 0;
        #pragma unroll
        for (int e = 1; e < EE; e++) if (logits[e] > mx) { mx = logits[e]; arg = e; }
        float ex[EE], den = 0.f;
        #pragma unroll
        for (int e = 0; e < EE; e++) { ex[e] = expf(logits[e] - mx); den += ex[e]; }
        if (write_aux) {
            const float inv = 1.0f / den;
            #pragma unroll
            for (int e = 0; e < EE; e++) out[FINAL_ELEMS + b * EE + e] = ex[e] * inv;
            out[FINAL_ELEMS + BB * EE + b] = (float)arg;
        }
        g_expert[b] = arg;
    }
}

// ---------------- HMMA GEMM (mma.sync, split-bf16 3-term) -------------------
// R8-proven core: KC=32, issue-cp.async-THEN-wait. New: 4-stage ring (&3
// addressing) -> single __syncthreads per iteration; MT template for block-M.
// Block (MT*64)x128, 8 warps (4Mx2N), warp tile (MT*16)x64.
#define KC 32
#define NSTAGE 4

// smem byte offset for (row r, 16B-chunk c in 0..3) with swizzle (R8 layout)
__device__ __forceinline__ uint32_t swoff(int r, int c) {
    return (uint32_t)(r * 64 + ((c ^ ((r >> 1) & 3)) << 4));
}

template<int MT, bool RELU, bool SPLIT_OUT>
__device__ __forceinline__ void gemm_hmma(
    const __nv_bfloat16* __restrict__ Ahi, const __nv_bfloat16* __restrict__ Alo,
    const __nv_bfloat16* __restrict__ Bhi, const __nv_bfloat16* __restrict__ Blo,
    const float* __restrict__ bias, int K,
    float* __restrict__ outF, __nv_bfloat16* __restrict__ outHi,
    __nv_bfloat16* __restrict__ outLo, int Nld) {

    constexpr int A_ROWS = MT * 64;                 // block M
    constexpr uint32_t A_BYTES = (uint32_t)A_ROWS * 64;   // KC=32 bf16 = 64B/row
    constexpr uint32_t AHI_OFF = 0;
    constexpr uint32_t ALO_OFF = A_BYTES;
    constexpr uint32_t BHI_OFF = 2 * A_BYTES;
    constexpr uint32_t BLO_OFF = 2 * A_BYTES + 8192;
    constexpr uint32_t STAGE_B = 2 * A_BYTES + 16384;

    extern __shared__ char smem[];
    const uint32_t sb = smem_u32(smem);
    const int tid = threadIdx.x;
    const int wid = tid >> 5, lane = tid & 31;
    const int wm = wid & 3, wn = wid >> 2;          // 4 x 2 warp grid
    const int row0 = blockIdx.y * A_ROWS;
    const int col0 = blockIdx.x * 128;

    float acc[MT][8][4];
    #pragma unroll
    for (int i = 0; i < MT; i++)
        #pragma unroll
        for (int j = 0; j < 8; j++)
            #pragma unroll
            for (int k = 0; k < 4; k++) acc[i][j][k] = 0.f;

    const int nk = K / KC;
    const int sr = tid >> 2, sc = tid & 3;          // staging rows/chunks

    // ---- stage chunk IDX into ring buffer IDX&3 (commit at end) ----
    #define STAGE(IDX)                                                          \
    do {                                                                        \
        const int _i = (IDX);                                                   \
        const uint32_t _d = sb + (uint32_t)(_i & 3) * STAGE_B;                  \
        const int _kb = _i * KC;                                                \
        _Pragma("unroll")                                                       \
        for (int p = 0; p < MT; p++) {          /* A: A_ROWS rows */            \
            const int r = sr + p * 64;                                          \
            const uint32_t so = swoff(r, sc);                                   \
            const size_t ga = (size_t)(row0 + r) * K + _kb + sc * 8;            \
            CP_ASYNC16(_d + AHI_OFF + so, Ahi + ga);                            \
            CP_ASYNC16(_d + ALO_OFF + so, Alo + ga);                            \
        }                                                                       \
        _Pragma("unroll")                                                       \
        for (int p = 0; p < 2; p++) {           /* B: 128 rows */               \
            const int r = sr + p * 64;                                          \
            const uint32_t so = swoff(r, sc);                                   \
            const size_t gb = (size_t)(col0 + r) * K + _kb + sc * 8;            \
            CP_ASYNC16(_d + BHI_OFF + so, Bhi + gb);                            \
            CP_ASYNC16(_d + BLO_OFF + so, Blo + gb);                            \
        }                                                                       \
        CP_COMMIT();                                                            \
    } while (0)

    // prologue: 2 stages in flight (nk >= 4 in all uses)
    STAGE(0);
    STAGE(1);

    // fragment address parameters (constant across loop)
    const int a_mrow = lane & 15, a_kh = lane >> 4;
    const int b_nr = lane & 7, b_kh = (lane >> 3) & 1, b_nt = lane >> 4;

    for (int i = 0; i < nk; i++) {
        // R8 ordering: issue next stage FIRST, then wait for stage i.
        // Writes target buf (i+2)&3 == (i-2)&3; lagging warps read only
        // (i-1)&3 or i&3 (skew < 1 iter via the single sync) -> disjoint.
        if (i + 2 < nk)      { STAGE(i + 2); CP_WAIT(2); }
        else if (i + 1 < nk) { CP_WAIT(1); }
        else                 { CP_WAIT(0); }
        __syncthreads();                 // single barrier per iteration

        const uint32_t st = sb + (uint32_t)(i & 3) * STAGE_B;
        #pragma unroll
        for (int ks = 0; ks < 2; ks++) {
            uint32_t ah[MT][4], al[MT][4];
            #pragma unroll
            for (int mt = 0; mt < MT; mt++) {
                const int r = wm * (16 * MT) + mt * 16 + a_mrow;
                const uint32_t ad = st + swoff(r, ks * 2 + a_kh);
                ldsm4(ah[mt], ad + AHI_OFF);
                ldsm4(al[mt], ad + ALO_OFF);
            }
            uint32_t bh[8][2], bl[8][2];
            #pragma unroll
            for (int ng = 0; ng < 4; ng++) {
                const int r = wn * 64 + ng * 16 + b_nt * 8 + b_nr;
                const uint32_t bd = st + swoff(r, ks * 2 + b_kh);
                uint32_t t4[4];
                ldsm4(t4, bd + BHI_OFF);
                bh[ng * 2][0] = t4[0]; bh[ng * 2][1] = t4[1];
                bh[ng * 2 + 1][0] = t4[2]; bh[ng * 2 + 1][1] = t4[3];
                ldsm4(t4, bd + BLO_OFF);
                bl[ng * 2][0] = t4[0]; bl[ng * 2][1] = t4[1];
                bl[ng * 2 + 1][0] = t4[2]; bl[ng * 2 + 1][1] = t4[3];
            }
            #pragma unroll
            for (int mt = 0; mt < MT; mt++)
                #pragma unroll
                for (int nt = 0; nt < 8; nt++) {
                    mma16816(acc[mt][nt], ah[mt], bh[nt]);   // hi*hi
                    mma16816(acc[mt][nt], ah[mt], bl[nt]);   // hi*lo
                    mma16816(acc[mt][nt], al[mt], bh[nt]);   // lo*hi
                }
        }
        // no trailing sync: 4-deep ring keeps writer/reader buffers disjoint
    }
    #undef STAGE

    // ---- epilogue: bias (+relu), direct stores ----
    const int erow = lane >> 2, ecol = (lane & 3) * 2;
    #pragma unroll
    for (int mt = 0; mt < MT; mt++) {
        #pragma unroll
        for (int nt = 0; nt < 8; nt++) {
            const int col = col0 + wn * 64 + nt * 8 + ecol;
            const float bx = __ldg(bias + col), by = __ldg(bias + col + 1);
            float v[4];
            v[0] = acc[mt][nt][0] + bx; v[1] = acc[mt][nt][1] + by;
            v[2] = acc[mt][nt][2] + bx; v[3] = acc[mt][nt][3] + by;
            if (RELU) {
                #pragma unroll
                for (int q = 0; q < 4; q++) v[q] = fmaxf(v[q], 0.f);
            }
            const size_t r0g = (size_t)(row0 + wm * (16 * MT) + mt * 16 + erow);
            #pragma unroll
            for (int half = 0; half < 2; half++) {
                const size_t row = r0g + half * 8;
                const float v0 = v[half * 2], v1 = v[half * 2 + 1];
                if (SPLIT_OUT) {
                    __nv_bfloat16 h0, l0, h1, l1;
                    split2(v0, h0, l0); split2(v1, h1, l1);
                    *(uint32_t*)(outHi + row * Nld + col) =
                        ((uint32_t)__bfloat16_as_ushort(h1) << 16) | __bfloat16_as_ushort(h0);
                    *(uint32_t*)(outLo + row * Nld + col) =
                        ((uint32_t)__bfloat16_as_ushort(l1) << 16) | __bfloat16_as_ushort(l0);
                } else {
                    float2 f2; f2.x = v0; f2.y = v1;
                    *(float2*)(outF + row * Nld + col) = f2;
                }
            }
        }
    }
}

// stage sizes (host-visible): STAGE_B = 2*A_BYTES + 16K; A_BYTES = MT*64*64
#define G1_SMEM (NSTAGE * (2 * (2 * 64 * 64) + 16384))   // MT=2: 4*32K = 128K
#define G2_SMEM (NSTAGE * (2 * (1 * 64 * 64) + 16384))   // MT=1: 4*24K = 96K

// GEMM1: h = relu(x @ W1[e] + b1[e])   M=512, N=2048, K=512  (128x128 tiles)
__global__ void __launch_bounds__(256, 1)
gemm1_mm(const float* __restrict__ b1) {
    const int b = blockIdx.z;
    const int e = g_expert[b];
    gemm_hmma<2, true, true>(g_x_hi + (size_t)b * TT * DD, g_x_lo + (size_t)b * TT * DD,
                             g_w1_hi + (size_t)e * HH * DD, g_w1_lo + (size_t)e * HH * DD,
                             b1 + e * HH, DD,
                             nullptr, g_h_hi + (size_t)b * TT * HH, g_h_lo + (size_t)b * TT * HH, HH);
}

// GEMM2: out = h @ W2[e] + b2[e]       M=512, N=512, K=2048  (64x128 tiles:
// 1024 CTAs -> 6.92 waves instead of 3.46 -> tail loss 13% -> ~1%)
__global__ void __launch_bounds__(256, 1)
gemm2_mm(const float* __restrict__ b2, float* __restrict__ out) {
    const int b = blockIdx.z;
    const int e = g_expert[b];
    gemm_hmma<1, false, false>(g_h_hi + (size_t)b * TT * HH, g_h_lo + (size_t)b * TT * HH,
                               g_w2_hi + (size_t)e * DD * HH, g_w2_lo + (size_t)e * DD * HH,
                               b2 + e * DD, HH,
                               out + (size_t)b * TT * DD, nullptr, nullptr, DD);
}

// ---------------- launch ----------------------------------------------------
extern "C" void kernel_launch(void* const* d_in, const int* in_sizes, int n_in,
                              void* d_out, int out_size) {
    const float* x  = (const float*)d_in[0];
    const float* Wp = (const float*)d_in[1];
    const float* bp = (const float*)d_in[2];
    const float* W1 = (const float*)d_in[3];
    const float* b1 = (const float*)d_in[4];
    const float* W2 = (const float*)d_in[5];
    const float* b2 = (const float*)d_in[6];
    float* out = (float*)d_out;

    const int write_aux = (out_size >= FINAL_ELEMS + BB * EE + BB) ? 1 : 0;

    cudaFuncSetAttribute(gemm1_mm, cudaFuncAttributeMaxDynamicSharedMemorySize, G1_SMEM);
    cudaFuncSetAttribute(gemm2_mm, cudaFuncAttributeMaxDynamicSharedMemorySize, G2_SMEM);

    split_pool_x_kernel<<<dim3(BB, 16), 256>>>(x);
    transpose_split_kernel<<<dim3(HH / 32, DD / 32, EE), dim3(32, 8)>>>(W1, DD, HH, 0);
    transpose_split_kernel<<<dim3(DD / 32, HH / 32, EE), dim3(32, 8)>>>(W2, HH, DD, 1);
    router_kernel<<<BB, 256>>>(Wp, bp, out, write_aux);
    gemm1_mm<<<dim3(HH / 128, TT / 128, BB), 256, G1_SMEM>>>(b1);
    gemm2_mm<<<dim3(DD / 128, TT / 64, BB), 256, G2_SMEM>>>(b2, out);
}